// round 7
// baseline (speedup 1.0000x reference)
#include <cuda_runtime.h>
#include <cuda_bf16.h>

#define DIM      4096
#define THREADS  256
#define EPT      16

__device__ __forceinline__ void fwht16(float v[EPT]) {
#pragma unroll
    for (int h = 1; h < EPT; h <<= 1) {
#pragma unroll
        for (int i = 0; i < EPT; i++) {
            if ((i & h) == 0) {
                float a = v[i];
                float b = v[i | h];
                v[i]     = a + b;
                v[i | h] = a - b;
            }
        }
    }
}

// Physical smem layout: word A(i) = i ^ G(i), G(i) = b5 | b6*6 | b7*8 | b8*16
// (b_j = bit j of logical index i). Bank functionals (A bits 0-4):
//   (b0^b5, b1^b6, b2^b6, b3^b7, b4^b8)
// -> injective on each phase's lane-varying bit set => conflict-free everywhere.

__global__ __launch_bounds__(THREADS, 7)
void fwht4096_kernel(const float* __restrict__ x, float* __restrict__ y) {
    __shared__ float s[DIM];

    const int row = blockIdx.x;
    const float* __restrict__ xr = x + (size_t)row * DIM;
    float* __restrict__       yr = y + (size_t)row * DIM;
    const int t = threadIdx.x;

    float v[EPT];

    // ---- Phase A: bits {b0,b1,b10,b11}; i = g*1024 + 4t + c ----
    // Coalesced: instruction g reads f4-indices g*256 + t (contiguous per warp).
    const float4* __restrict__ x4 = reinterpret_cast<const float4*>(xr);
#pragma unroll
    for (int g = 0; g < 4; g++) {
        float4 f = __ldcs(x4 + g * 256 + t);
        v[4 * g + 0] = f.x;
        v[4 * g + 1] = f.y;
        v[4 * g + 2] = f.z;
        v[4 * g + 3] = f.w;
    }
    fwht16(v);

    // A-write: i bits 5-8 = t bits 3-6 -> G thread-constant, fully hoisted.
    {
        const int GA = ((t >> 2) & 28) | ((t >> 3) & 3);
        float* s0 = s + ((4 * t) ^ (GA & 28));
        const int ca = GA & 3;
        float* p0 = s0 + (0 ^ ca);
        float* p1 = s0 + (1 ^ ca);
        float* p2 = s0 + (2 ^ ca);
        float* p3 = s0 + (3 ^ ca);
#pragma unroll
        for (int g = 0; g < 4; g++) {
            p0[g * 1024] = v[4 * g + 0];
            p1[g * 1024] = v[4 * g + 1];
            p2[g * 1024] = v[4 * g + 2];
            p3[g * 1024] = v[4 * g + 3];
        }
    }
    __syncthreads();

    const int e = t & 3;
    const int m = (t >> 2) & 15;
    const int d = t >> 6;

    // ---- Phase B: bits {b2..b5}; i = d*1024 + m*64 + 4k + e ----
    // A(i): bits2-4 = (k&7)^(m&7); bit5 = k3; bit1 ^= m0; bit0 ^= k3.
    {
        const int PB  = d * 1024 + m * 64 + (e ^ ((m & 1) << 1)) + ((m & 7) << 2);
        const int PB2 = (PB + 32) ^ 1;
#pragma unroll
        for (int k = 0; k < EPT; k++) {
            int a = ((k < 8) ? PB : PB2) ^ ((4 * k) & 28);
            v[k] = s[a];
        }
        fwht16(v);
        // read set == write set per thread; sets partition smem -> no sync here
#pragma unroll
        for (int k = 0; k < EPT; k++) {
            int a = ((k < 8) ? PB : PB2) ^ ((4 * k) & 28);
            s[a] = v[k];
        }
    }
    __syncthreads();

    // ---- Phase C: bits {b6..b9}; i = d*1024 + 64k + 4m + e ----
    // A(i): bits2-4 = (m&7)^(k&7); bit1 ^= k0; bit0 ^= m3; bit5 = m3.
    {
        const int PC = d * 1024 + 4 * m + (e ^ (m >> 3));
#pragma unroll
        for (int k = 0; k < EPT; k++) {
            const int Qk = ((k & 7) << 2) | ((k & 1) << 1);
            v[k] = s[(PC ^ Qk) + 64 * k];
        }
        fwht16(v);

        // scale by 1/sqrt(4096); stores: lanes cover b0..b4 -> 128B coalesced
        const float scale = 0.015625f;
        const int baseL = d * 1024 + 4 * m + e;
#pragma unroll
        for (int k = 0; k < EPT; k++) {
            __stcs(yr + baseL + 64 * k, v[k] * scale);
        }
    }
}

extern "C" void kernel_launch(void* const* d_in, const int* in_sizes, int n_in,
                              void* d_out, int out_size) {
    const float* x = (const float*)d_in[0];
    float* y = (float*)d_out;
    int rows = in_sizes[0] / DIM;   // 8192
    fwht4096_kernel<<<rows, THREADS>>>(x, y);
}